// round 15
// baseline (speedup 1.0000x reference)
#include <cuda_runtime.h>
#include <cuda_fp16.h>
#include <cstdint>
#include <cstddef>

#define S_LEN 2048
#define HID   1024
#define NH    16
#define HD    64
#define BATCH 2
#define M_TOT (BATCH * S_LEN)   // 4096

// ---------------- scratch (static device arrays; no allocation) -------------
__device__ __half g_Xh[(size_t)M_TOT * HID];
__device__ __half g_Wh[3ull * HID * HID];
__device__ __half g_Qh[(size_t)M_TOT * HID];
__device__ __half g_Kh[(size_t)M_TOT * HID];
__device__ __half g_Vt[(size_t)BATCH * NH * HD * S_LEN];  // [(b*NH+h)*HD+hd][s]

// ---------------- helpers ---------------------------------------------------
__device__ __forceinline__ void mma_f16(float d[4], const uint32_t a[4],
                                        uint32_t b0, uint32_t b1) {
    asm volatile(
        "mma.sync.aligned.m16n8k16.row.col.f32.f16.f16.f32 "
        "{%0,%1,%2,%3}, {%4,%5,%6,%7}, {%8,%9}, {%0,%1,%2,%3};\n"
        : "+f"(d[0]), "+f"(d[1]), "+f"(d[2]), "+f"(d[3])
        : "r"(a[0]), "r"(a[1]), "r"(a[2]), "r"(a[3]), "r"(b0), "r"(b1));
}
__device__ __forceinline__ uint32_t pack2(float lo, float hi) {
    __half2 h = __floats2half2_rn(lo, hi);
    return *reinterpret_cast<uint32_t*>(&h);
}
__device__ __forceinline__ uint32_t ldh2(const __half* p) {
    return *reinterpret_cast<const uint32_t*>(p);
}
// exp(s/8) = ex2(s * log2(e)/8); folded constant, one FMUL + MUFU.EX2
#define EXPC 0.18033688f
__device__ __forceinline__ float fexp2(float x) {
    float r;
    asm("ex2.approx.ftz.f32 %0, %1;" : "=f"(r) : "f"(x));
    return r;
}
// streaming store for probs (write-once, never re-read): evict-first in L2
__device__ __forceinline__ void stg_cs2(float* p, float x, float y) {
    asm volatile("st.global.cs.v2.f32 [%0], {%1, %2};" :: "l"(p), "f"(x), "f"(y)
                 : "memory");
}
__device__ __forceinline__ void cp16(uint32_t dst, const void* src) {
    asm volatile("cp.async.cg.shared.global [%0], [%1], 16;" :: "r"(dst), "l"(src));
}
__device__ __forceinline__ void cp_commit() {
    asm volatile("cp.async.commit_group;");
}
__device__ __forceinline__ void cp_wait1() { asm volatile("cp.async.wait_group 1;"); }
__device__ __forceinline__ void cp_wait0() { asm volatile("cp.async.wait_group 0;"); }

// ============================================================================
// Kernel 0: fp32 -> fp16 conversion of X, Wq, Wk, Wv
// ============================================================================
#define NX4 ((size_t)M_TOT * HID / 4)        // 1048576
#define NW4 ((size_t)HID * HID / 4)          // 262144
#define NCVT (NX4 + 3 * NW4)

__global__ __launch_bounds__(256) void cvt_kernel(
    const float* __restrict__ X, const float* __restrict__ Wq,
    const float* __restrict__ Wk, const float* __restrict__ Wv)
{
    size_t i = (size_t)blockIdx.x * blockDim.x + threadIdx.x;
    if (i >= NCVT) return;
    const float* src; __half* dst; size_t j;
    if (i < NX4)                { src = X;  dst = g_Xh;            j = i; }
    else if (i < NX4 + NW4)     { src = Wq; dst = g_Wh;            j = i - NX4; }
    else if (i < NX4 + 2 * NW4) { src = Wk; dst = g_Wh + NW4 * 4;  j = i - NX4 - NW4; }
    else                        { src = Wv; dst = g_Wh + NW4 * 8;  j = i - NX4 - 2 * NW4; }
    float4 v = *reinterpret_cast<const float4*>(src + 4 * j);
    __half2 h0 = __floats2half2_rn(v.x, v.y);
    __half2 h1 = __floats2half2_rn(v.z, v.w);
    uint2 out = { *reinterpret_cast<uint32_t*>(&h0), *reinterpret_cast<uint32_t*>(&h1) };
    *reinterpret_cast<uint2*>(dst + 4 * j) = out;
}

// ============================================================================
// Kernel 1: QKV projection. fp16 cp.async GEMM, CTA 128x128, BK=64, 512 thr.
// 16 warps = 8(m) x 2(n), warp tile 16x64 (acc=32 regs/thread -> no spills,
// 2x warps/SM vs the 256-thr variant). 3-stage single-sync pipeline.
// ============================================================================
#define QSTR 72                               // smem row stride in halves
#define QSZ  (128 * QSTR * 2)                 // 18432 B per tile
#define QSA(i) ((i) * QSZ)
#define QSB(i) (3 * QSZ + (i) * QSZ)
#define QKV_SMEM (6 * QSZ)                    // 110592 B

__device__ __forceinline__ void qkv_load(uint32_t sbase, const __half* g,
                                         int row0, int kt, int tid) {
#pragma unroll
    for (int j = 0; j < 2; j++) {
        int id = tid + j * 512;               // 1024 chunks of 16B
        int r = id >> 3, ch = id & 7;
        cp16(sbase + (uint32_t)(r * QSTR + ch * 8) * 2,
             g + (size_t)(row0 + r) * HID + kt * 64 + ch * 8);
    }
}

__global__ __launch_bounds__(512, 1) void qkv_kernel(
    const float* __restrict__ bq, const float* __restrict__ bk,
    const float* __restrict__ bv)
{
    extern __shared__ char smq[];
    const uint32_t smb = (uint32_t)__cvta_generic_to_shared(smq);
    const int z = blockIdx.z;
    const __half* A = g_Xh;
    const __half* Bm = g_Wh + (size_t)z * HID * HID;
    const float* bias = (z == 0) ? bq : (z == 1) ? bk : bv;

    const int tid = threadIdx.x, wid = tid >> 5, lane = tid & 31;
    const int g = lane >> 2, tig = lane & 3;
    const int wm = wid & 7, wn = wid >> 3;
    const int m0 = blockIdx.y * 128, n0 = blockIdx.x * 128;

    float acc[8][4];
#pragma unroll
    for (int j = 0; j < 8; j++)
#pragma unroll
        for (int k = 0; k < 4; k++) acc[j][k] = 0.f;

    qkv_load(smb + QSA(0), A, m0, 0, tid);
    qkv_load(smb + QSB(0), Bm, n0, 0, tid);
    cp_commit();
    qkv_load(smb + QSA(1), A, m0, 1, tid);
    qkv_load(smb + QSB(1), Bm, n0, 1, tid);
    cp_commit();

    for (int kt = 0; kt < 16; kt++) {
        if (kt < 15) cp_wait1(); else cp_wait0();
        __syncthreads();
        if (kt + 2 < 16) {
            const int s = (kt + 2) % 3;
            qkv_load(smb + QSA(s), A, m0, kt + 2, tid);
            qkv_load(smb + QSB(s), Bm, n0, kt + 2, tid);
            cp_commit();
        }
        const __half* sA = reinterpret_cast<const __half*>(smq + QSA(kt % 3));
        const __half* sB = reinterpret_cast<const __half*>(smq + QSB(kt % 3));
#pragma unroll
        for (int ks = 0; ks < 4; ks++) {
            const int kb = ks * 16;
            uint32_t af[4];
            const __half* ap = sA + (wm * 16 + g) * QSTR + kb + 2 * tig;
            af[0] = ldh2(ap);
            af[1] = ldh2(ap + 8 * QSTR);
            af[2] = ldh2(ap + 8);
            af[3] = ldh2(ap + 8 * QSTR + 8);
#pragma unroll
            for (int nt = 0; nt < 8; nt++) {
                const __half* bp = sB + (wn * 64 + nt * 8 + g) * QSTR + kb + 2 * tig;
                uint32_t b0 = ldh2(bp), b1 = ldh2(bp + 8);
                mma_f16(acc[nt], af, b0, b1);
            }
        }
    }
    __syncthreads();

    if (z < 2) {
        __half* Y = (z == 0) ? g_Qh : g_Kh;
        const int r = m0 + wm * 16 + g;
#pragma unroll
        for (int nt = 0; nt < 8; nt++) {
            const int c = n0 + wn * 64 + nt * 8 + 2 * tig;
            const float b0 = bias[c], b1 = bias[c + 1];
            *reinterpret_cast<__half2*>(&Y[(size_t)r * HID + c]) =
                __floats2half2_rn(acc[nt][0] + b0, acc[nt][1] + b1);
            *reinterpret_cast<__half2*>(&Y[(size_t)(r + 8) * HID + c]) =
                __floats2half2_rn(acc[nt][2] + b0, acc[nt][3] + b1);
        }
    } else {
        // V: transpose through SMEM, then coalesced stores to g_Vt[(b,h,hd)][s]
        __half* sT = reinterpret_cast<__half*>(smq);   // [128 cols][136] stride
        const int rl = wm * 16 + g;
#pragma unroll
        for (int nt = 0; nt < 8; nt++) {
            const int cl = wn * 64 + nt * 8 + 2 * tig;
            const float b0 = bias[n0 + cl], b1 = bias[n0 + cl + 1];
            sT[cl * 136 + rl]           = __float2half(acc[nt][0] + b0);
            sT[(cl + 1) * 136 + rl]     = __float2half(acc[nt][1] + b1);
            sT[cl * 136 + rl + 8]       = __float2half(acc[nt][2] + b0);
            sT[(cl + 1) * 136 + rl + 8] = __float2half(acc[nt][3] + b1);
        }
        __syncthreads();
        const int bb = m0 >> 11;
        const int s0 = m0 & 2047;
#pragma unroll
        for (int j = 0; j < 4; j++) {
            int id = tid + j * 512;       // 2048 chunks of 16B
            int cl = id >> 4, ch = id & 15;
            int c = n0 + cl;
            int hh = c >> 6, hd = c & 63;
            *reinterpret_cast<uint4*>(
                g_Vt + ((size_t)(bb * NH + hh) * HD + hd) * S_LEN + s0 + ch * 8) =
                *reinterpret_cast<const uint4*>(sT + cl * 136 + ch * 8);
        }
    }
}

// ============================================================================
// Kernel 2: attention.  fp16 mma, 3-stage cp.async, single sync per tile,
// register-resident Q and P.  256 thr, 8 warps = 4(m) x 2(n).
// (round-14 proven: .cs probs stores + folded ex2)
// ============================================================================
#define SKW 72    // K tile stride (halves): 128 rows x 64 hd
#define SVW 136   // Vt tile stride (halves): 64 hd rows x 128 s
#define SZK (128 * SKW * 2)     // 18432
#define SZV (64 * SVW * 2)      // 17408
#define OFF_KB(i) ((i) * SZK)
#define OFF_VB(i) (3 * SZK + (i) * SZV)
#define OFF_SL    (3 * SZK + 3 * SZV)
#define ATTN_SMEM (OFF_SL + 512)    // 108032

__device__ __forceinline__ void load_k_tile(uint32_t sbase, const __half* Kg,
                                            int k0, int tid) {
#pragma unroll
    for (int j = 0; j < 4; j++) {
        int id = tid + j * 256;
        int r = id >> 3, ch = id & 7;
        cp16(sbase + (uint32_t)(r * SKW + ch * 8) * 2,
             Kg + (size_t)(k0 + r) * HID + ch * 8);
    }
}
__device__ __forceinline__ void load_v_tile(uint32_t sbase, const __half* Vt,
                                            int k0, int tid) {
#pragma unroll
    for (int j = 0; j < 4; j++) {
        int id = tid + j * 256;
        int hd = id >> 4, ch = id & 15;
        cp16(sbase + (uint32_t)(hd * SVW + ch * 8) * 2,
             Vt + (size_t)hd * S_LEN + k0 + ch * 8);
    }
}

__global__ __launch_bounds__(256, 1) void attn_kernel(
    float* __restrict__ ctx_out, float* __restrict__ probs_out)
{
    extern __shared__ char sm[];
    const uint32_t smb = (uint32_t)__cvta_generic_to_shared(sm);
    const int tid = threadIdx.x, wid = tid >> 5, lane = tid & 31;
    const int g = lane >> 2, tig = lane & 3;
    const int wm = wid & 3, wn = wid >> 2;
    const int q0 = blockIdx.x * 128, h = blockIdx.y, b = blockIdx.z;

    const __half* Qg = g_Qh + (size_t)b * S_LEN * HID + (size_t)h * HD;
    const __half* Kg = g_Kh + (size_t)b * S_LEN * HID + (size_t)h * HD;
    const __half* Vt = g_Vt + (size_t)(b * NH + h) * HD * S_LEN;
    float* sL = reinterpret_cast<float*>(sm + OFF_SL);

    // Q fragments: register-resident for the whole kernel
    uint32_t qf[4][2][4];
#pragma unroll
    for (int ks = 0; ks < 4; ks++)
#pragma unroll
        for (int mt = 0; mt < 2; mt++) {
            const __half* qp = Qg + (size_t)(q0 + wm * 32 + mt * 16 + g) * HID
                               + ks * 16 + 2 * tig;
            qf[ks][mt][0] = ldh2(qp);
            qf[ks][mt][1] = ldh2(qp + 8 * HID);
            qf[ks][mt][2] = ldh2(qp + 8);
            qf[ks][mt][3] = ldh2(qp + 8 * HID + 8);
        }

    if (tid < 128) sL[tid] = 0.f;
    __syncthreads();

    // ---------------- sweep 1: denominators ----------------
    load_k_tile(smb + OFF_KB(0), Kg, 0, tid); cp_commit();
    load_k_tile(smb + OFF_KB(1), Kg, 128, tid); cp_commit();
    float rs[4] = {0.f, 0.f, 0.f, 0.f};

    for (int kt = 0; kt < 16; kt++) {
        if (kt < 15) cp_wait1(); else cp_wait0();
        __syncthreads();
        if (kt + 2 < 16) {
            load_k_tile(smb + OFF_KB((kt + 2) % 3), Kg, (kt + 2) * 128, tid);
            cp_commit();
        }
        const __half* sK = reinterpret_cast<const __half*>(sm + OFF_KB(kt % 3));
        float accS[2][8][4];
#pragma unroll
        for (int i = 0; i < 2; i++)
#pragma unroll
            for (int j = 0; j < 8; j++)
#pragma unroll
                for (int k = 0; k < 4; k++) accS[i][j][k] = 0.f;
#pragma unroll
        for (int ks = 0; ks < 4; ks++)
#pragma unroll
            for (int nt = 0; nt < 8; nt++) {
                const __half* bp = sK + (wn * 64 + nt * 8 + g) * SKW + ks * 16 + 2 * tig;
                uint32_t b0 = ldh2(bp), b1 = ldh2(bp + 8);
                mma_f16(accS[0][nt], qf[ks][0], b0, b1);
                mma_f16(accS[1][nt], qf[ks][1], b0, b1);
            }
#pragma unroll
        for (int mt = 0; mt < 2; mt++)
#pragma unroll
            for (int nt = 0; nt < 8; nt++) {
                rs[mt * 2]     += fexp2(accS[mt][nt][0] * EXPC) + fexp2(accS[mt][nt][1] * EXPC);
                rs[mt * 2 + 1] += fexp2(accS[mt][nt][2] * EXPC) + fexp2(accS[mt][nt][3] * EXPC);
            }
    }
#pragma unroll
    for (int o = 1; o < 4; o <<= 1)
#pragma unroll
        for (int j = 0; j < 4; j++) rs[j] += __shfl_xor_sync(0xffffffffu, rs[j], o);
    __syncthreads();          // all warps done with K buffers + sL zeroed visible
    if (tig == 0) {
        atomicAdd(&sL[wm * 32      + g], rs[0]);
        atomicAdd(&sL[wm * 32 + 8  + g], rs[1]);
        atomicAdd(&sL[wm * 32 + 16 + g], rs[2]);
        atomicAdd(&sL[wm * 32 + 24 + g], rs[3]);
    }
    __syncthreads();
    float rinv[4];
#pragma unroll
    for (int j = 0; j < 4; j++) rinv[j] = 1.0f / sL[wm * 32 + j * 8 + g];
    __syncthreads();

    // ---------------- sweep 2: probs + ctx ----------------
    load_k_tile(smb + OFF_KB(0), Kg, 0, tid);
    load_v_tile(smb + OFF_VB(0), Vt, 0, tid);
    cp_commit();
    load_k_tile(smb + OFF_KB(1), Kg, 128, tid);
    load_v_tile(smb + OFF_VB(1), Vt, 128, tid);
    cp_commit();

    float accO[2][8][4];
#pragma unroll
    for (int i = 0; i < 2; i++)
#pragma unroll
        for (int j = 0; j < 8; j++)
#pragma unroll
            for (int k = 0; k < 4; k++) accO[i][j][k] = 0.f;

    const size_t pb = ((size_t)(b * NH + h) * S_LEN + q0) * S_LEN;

    for (int kt = 0; kt < 16; kt++) {
        if (kt < 15) cp_wait1(); else cp_wait0();
        __syncthreads();
        if (kt + 2 < 16) {
            load_k_tile(smb + OFF_KB((kt + 2) % 3), Kg, (kt + 2) * 128, tid);
            load_v_tile(smb + OFF_VB((kt + 2) % 3), Vt, (kt + 2) * 128, tid);
            cp_commit();
        }
        const __half* sK  = reinterpret_cast<const __half*>(sm + OFF_KB(kt % 3));
        const __half* sVt = reinterpret_cast<const __half*>(sm + OFF_VB(kt % 3));

        float accS[2][8][4];
#pragma unroll
        for (int i = 0; i < 2; i++)
#pragma unroll
            for (int j = 0; j < 8; j++)
#pragma unroll
                for (int k = 0; k < 4; k++) accS[i][j][k] = 0.f;
#pragma unroll
        for (int ks = 0; ks < 4; ks++)
#pragma unroll
            for (int nt = 0; nt < 8; nt++) {
                const __half* bp = sK + (wn * 64 + nt * 8 + g) * SKW + ks * 16 + 2 * tig;
                uint32_t b0 = ldh2(bp), b1 = ldh2(bp + 8);
                mma_f16(accS[0][nt], qf[ks][0], b0, b1);
                mma_f16(accS[1][nt], qf[ks][1], b0, b1);
            }

        // exp + normalize, streaming-store probs, keep p in accS
#pragma unroll
        for (int mt = 0; mt < 2; mt++) {
            const int r0 = wm * 32 + mt * 16 + g;
#pragma unroll
            for (int nt = 0; nt < 8; nt++) {
                float p0 = fexp2(accS[mt][nt][0] * EXPC) * rinv[mt * 2];
                float p1 = fexp2(accS[mt][nt][1] * EXPC) * rinv[mt * 2];
                float p2 = fexp2(accS[mt][nt][2] * EXPC) * rinv[mt * 2 + 1];
                float p3 = fexp2(accS[mt][nt][3] * EXPC) * rinv[mt * 2 + 1];
                accS[mt][nt][0] = p0; accS[mt][nt][1] = p1;
                accS[mt][nt][2] = p2; accS[mt][nt][3] = p3;
                const size_t cidx = (size_t)kt * 128 + wn * 64 + nt * 8 + 2 * tig;
                stg_cs2(probs_out + pb + (size_t)r0 * S_LEN + cidx, p0, p1);
                stg_cs2(probs_out + pb + (size_t)(r0 + 8) * S_LEN + cidx, p2, p3);
            }
        }

        // pack P into fp16 A-fragments (register-only)
        uint32_t ph[2][4][4];
#pragma unroll
        for (int mt = 0; mt < 2; mt++)
#pragma unroll
            for (int j = 0; j < 4; j++) {
                ph[mt][j][0] = pack2(accS[mt][2 * j][0],     accS[mt][2 * j][1]);
                ph[mt][j][1] = pack2(accS[mt][2 * j][2],     accS[mt][2 * j][3]);
                ph[mt][j][2] = pack2(accS[mt][2 * j + 1][0], accS[mt][2 * j + 1][1]);
                ph[mt][j][3] = pack2(accS[mt][2 * j + 1][2], accS[mt][2 * j + 1][3]);
            }

        // O += P * V  (this warp's 64-k slice; partial over wn)
#pragma unroll
        for (int j = 0; j < 4; j++)
#pragma unroll
            for (int nt = 0; nt < 8; nt++) {
                const __half* vp = sVt + (nt * 8 + g) * SVW + wn * 64 + j * 16 + 2 * tig;
                uint32_t b0 = ldh2(vp), b1 = ldh2(vp + 8);
                mma_f16(accO[0][nt], ph[0][j], b0, b1);
                mma_f16(accO[1][nt], ph[1][j], b0, b1);
            }
    }
    __syncthreads();   // K/V buffers dead; reuse base of smem for O reduction

    // ---------------- O reduction across wn halves + ctx write ----------------
    float* sRed = reinterpret_cast<float*>(sm);   // [128][68]
    if (wn == 0) {
#pragma unroll
        for (int mt = 0; mt < 2; mt++) {
            const int r = wm * 32 + mt * 16 + g;
#pragma unroll
            for (int nt = 0; nt < 8; nt++) {
                const int c = nt * 8 + 2 * tig;
                *reinterpret_cast<float2*>(&sRed[r * 68 + c]) =
                    make_float2(accO[mt][nt][0], accO[mt][nt][1]);
                *reinterpret_cast<float2*>(&sRed[(r + 8) * 68 + c]) =
                    make_float2(accO[mt][nt][2], accO[mt][nt][3]);
            }
        }
    }
    __syncthreads();
    if (wn == 1) {
#pragma unroll
        for (int mt = 0; mt < 2; mt++) {
            const int r = wm * 32 + mt * 16 + g;
#pragma unroll
            for (int nt = 0; nt < 8; nt++) {
                const int c = nt * 8 + 2 * tig;
                float2 a = *reinterpret_cast<float2*>(&sRed[r * 68 + c]);
                *reinterpret_cast<float2*>(&sRed[r * 68 + c]) =
                    make_float2(a.x + accO[mt][nt][0], a.y + accO[mt][nt][1]);
                float2 d = *reinterpret_cast<float2*>(&sRed[(r + 8) * 68 + c]);
                *reinterpret_cast<float2*>(&sRed[(r + 8) * 68 + c]) =
                    make_float2(d.x + accO[mt][nt][2], d.y + accO[mt][nt][3]);
            }
        }
    }
    __syncthreads();
    {
        const int row = tid >> 1, cb = (tid & 1) * 32;
        float* cw = ctx_out + (size_t)(b * S_LEN + q0 + row) * HID + h * HD + cb;
        const float* rr = sRed + row * 68 + cb;
#pragma unroll
        for (int i = 0; i < 8; i++)
            *reinterpret_cast<float4*>(cw + 4 * i) =
                *reinterpret_cast<const float4*>(rr + 4 * i);
    }
}

// ============================================================================
// launch
// ============================================================================
extern "C" void kernel_launch(void* const* d_in, const int* in_sizes, int n_in,
                              void* d_out, int out_size)
{
    const float* X  = (const float*)d_in[0];
    const float* Wq = (const float*)d_in[1];
    const float* bq = (const float*)d_in[2];
    const float* Wk = (const float*)d_in[3];
    const float* bk = (const float*)d_in[4];
    const float* Wv = (const float*)d_in[5];
    const float* bv = (const float*)d_in[6];

    float* ctx   = (float*)d_out;                         // [2,2048,1024]
    float* probs = ctx + (size_t)BATCH * S_LEN * HID;     // [2,16,2048,2048]

    cvt_kernel<<<(unsigned)((NCVT + 255) / 256), 256>>>(X, Wq, Wk, Wv);

    cudaFuncSetAttribute(qkv_kernel, cudaFuncAttributeMaxDynamicSharedMemorySize,
                         QKV_SMEM);
    qkv_kernel<<<dim3(HID / 128, M_TOT / 128, 3), 512, QKV_SMEM>>>(bq, bk, bv);

    cudaFuncSetAttribute(attn_kernel, cudaFuncAttributeMaxDynamicSharedMemorySize,
                         ATTN_SMEM);
    attn_kernel<<<dim3(S_LEN / 128, NH, BATCH), 256, ATTN_SMEM>>>(ctx, probs);
}

// round 16
// speedup vs baseline: 1.0484x; 1.0484x over previous
#include <cuda_runtime.h>
#include <cuda_fp16.h>
#include <cstdint>
#include <cstddef>

#define S_LEN 2048
#define HID   1024
#define NH    16
#define HD    64
#define BATCH 2
#define M_TOT (BATCH * S_LEN)   // 4096

// ---------------- scratch (static device arrays; no allocation) -------------
__device__ __half g_Xh[(size_t)M_TOT * HID];
__device__ __half g_Wh[3ull * HID * HID];
__device__ __half g_Qh[(size_t)M_TOT * HID];
__device__ __half g_Kh[(size_t)M_TOT * HID];
__device__ __half g_Vt[(size_t)BATCH * NH * HD * S_LEN];  // [(b*NH+h)*HD+hd][s]

// ---------------- helpers ---------------------------------------------------
__device__ __forceinline__ void mma_f16(float d[4], const uint32_t a[4],
                                        uint32_t b0, uint32_t b1) {
    asm volatile(
        "mma.sync.aligned.m16n8k16.row.col.f32.f16.f16.f32 "
        "{%0,%1,%2,%3}, {%4,%5,%6,%7}, {%8,%9}, {%0,%1,%2,%3};\n"
        : "+f"(d[0]), "+f"(d[1]), "+f"(d[2]), "+f"(d[3])
        : "r"(a[0]), "r"(a[1]), "r"(a[2]), "r"(a[3]), "r"(b0), "r"(b1));
}
__device__ __forceinline__ uint32_t pack2(float lo, float hi) {
    __half2 h = __floats2half2_rn(lo, hi);
    return *reinterpret_cast<uint32_t*>(&h);
}
__device__ __forceinline__ uint32_t ldh2(const __half* p) {
    return *reinterpret_cast<const uint32_t*>(p);
}
// exp(s/8) = ex2(s * log2(e)/8); folded constant, one FMUL + MUFU.EX2
#define EXPC 0.18033688f
__device__ __forceinline__ float fexp2(float x) {
    float r;
    asm("ex2.approx.ftz.f32 %0, %1;" : "=f"(r) : "f"(x));
    return r;
}
// half2 ex2: two exps per MUFU op (sweep-1 rowsums only; errors average out)
__device__ __forceinline__ uint32_t h2ex2(uint32_t h2) {
    uint32_t r;
    asm("ex2.approx.f16x2 %0, %1;" : "=r"(r) : "r"(h2));
    return r;
}
// streaming store for probs (write-once, never re-read): evict-first in L2
__device__ __forceinline__ void stg_cs2(float* p, float x, float y) {
    asm volatile("st.global.cs.v2.f32 [%0], {%1, %2};" :: "l"(p), "f"(x), "f"(y)
                 : "memory");
}
__device__ __forceinline__ void cp16(uint32_t dst, const void* src) {
    asm volatile("cp.async.cg.shared.global [%0], [%1], 16;" :: "r"(dst), "l"(src));
}
__device__ __forceinline__ void cp_commit() {
    asm volatile("cp.async.commit_group;");
}
__device__ __forceinline__ void cp_wait1() { asm volatile("cp.async.wait_group 1;"); }
__device__ __forceinline__ void cp_wait0() { asm volatile("cp.async.wait_group 0;"); }

// ============================================================================
// Kernel 0: fp32 -> fp16 conversion of X, Wq, Wk, Wv
// ============================================================================
#define NX4 ((size_t)M_TOT * HID / 4)        // 1048576
#define NW4 ((size_t)HID * HID / 4)          // 262144
#define NCVT (NX4 + 3 * NW4)

__global__ __launch_bounds__(256) void cvt_kernel(
    const float* __restrict__ X, const float* __restrict__ Wq,
    const float* __restrict__ Wk, const float* __restrict__ Wv)
{
    size_t i = (size_t)blockIdx.x * blockDim.x + threadIdx.x;
    if (i >= NCVT) return;
    const float* src; __half* dst; size_t j;
    if (i < NX4)                { src = X;  dst = g_Xh;            j = i; }
    else if (i < NX4 + NW4)     { src = Wq; dst = g_Wh;            j = i - NX4; }
    else if (i < NX4 + 2 * NW4) { src = Wk; dst = g_Wh + NW4 * 4;  j = i - NX4 - NW4; }
    else                        { src = Wv; dst = g_Wh + NW4 * 8;  j = i - NX4 - 2 * NW4; }
    float4 v = *reinterpret_cast<const float4*>(src + 4 * j);
    __half2 h0 = __floats2half2_rn(v.x, v.y);
    __half2 h1 = __floats2half2_rn(v.z, v.w);
    uint2 out = { *reinterpret_cast<uint32_t*>(&h0), *reinterpret_cast<uint32_t*>(&h1) };
    *reinterpret_cast<uint2*>(dst + 4 * j) = out;
}

// ============================================================================
// Kernel 1: QKV projection.  fp16 cp.async GEMM, CTA 128x128, BK=64, 256 thr,
// 8 warps 4(m) x 2(n), 3-stage single-sync pipeline.  (round-14 proven)
// ============================================================================
#define QSTR 72                               // smem row stride in halves
#define QSZ  (128 * QSTR * 2)                 // 18432 B per tile
#define QSA(i) ((i) * QSZ)
#define QSB(i) (3 * QSZ + (i) * QSZ)
#define QKV_SMEM (6 * QSZ)                    // 110592 B

__device__ __forceinline__ void qkv_load(uint32_t sbase, const __half* g,
                                         int row0, int kt, int tid) {
#pragma unroll
    for (int j = 0; j < 4; j++) {
        int id = tid + j * 256;               // 1024 chunks of 16B
        int r = id >> 3, ch = id & 7;
        cp16(sbase + (uint32_t)(r * QSTR + ch * 8) * 2,
             g + (size_t)(row0 + r) * HID + kt * 64 + ch * 8);
    }
}

__global__ __launch_bounds__(256, 1) void qkv_kernel(
    const float* __restrict__ bq, const float* __restrict__ bk,
    const float* __restrict__ bv)
{
    extern __shared__ char smq[];
    const uint32_t smb = (uint32_t)__cvta_generic_to_shared(smq);
    const int z = blockIdx.z;
    const __half* A = g_Xh;
    const __half* Bm = g_Wh + (size_t)z * HID * HID;
    const float* bias = (z == 0) ? bq : (z == 1) ? bk : bv;

    const int tid = threadIdx.x, wid = tid >> 5, lane = tid & 31;
    const int g = lane >> 2, tig = lane & 3;
    const int wm = wid & 3, wn = wid >> 2;
    const int m0 = blockIdx.y * 128, n0 = blockIdx.x * 128;

    float acc[2][8][4];
#pragma unroll
    for (int i = 0; i < 2; i++)
#pragma unroll
        for (int j = 0; j < 8; j++)
#pragma unroll
            for (int k = 0; k < 4; k++) acc[i][j][k] = 0.f;

    qkv_load(smb + QSA(0), A, m0, 0, tid);
    qkv_load(smb + QSB(0), Bm, n0, 0, tid);
    cp_commit();
    qkv_load(smb + QSA(1), A, m0, 1, tid);
    qkv_load(smb + QSB(1), Bm, n0, 1, tid);
    cp_commit();

    for (int kt = 0; kt < 16; kt++) {
        if (kt < 15) cp_wait1(); else cp_wait0();
        __syncthreads();
        if (kt + 2 < 16) {
            const int s = (kt + 2) % 3;
            qkv_load(smb + QSA(s), A, m0, kt + 2, tid);
            qkv_load(smb + QSB(s), Bm, n0, kt + 2, tid);
            cp_commit();
        }
        const __half* sA = reinterpret_cast<const __half*>(smq + QSA(kt % 3));
        const __half* sB = reinterpret_cast<const __half*>(smq + QSB(kt % 3));
#pragma unroll
        for (int ks = 0; ks < 4; ks++) {
            const int kb = ks * 16;
            uint32_t af[2][4];
#pragma unroll
            for (int mt = 0; mt < 2; mt++) {
                const __half* ap = sA + (wm * 32 + mt * 16 + g) * QSTR + kb + 2 * tig;
                af[mt][0] = ldh2(ap);
                af[mt][1] = ldh2(ap + 8 * QSTR);
                af[mt][2] = ldh2(ap + 8);
                af[mt][3] = ldh2(ap + 8 * QSTR + 8);
            }
#pragma unroll
            for (int nt = 0; nt < 8; nt++) {
                const __half* bp = sB + (wn * 64 + nt * 8 + g) * QSTR + kb + 2 * tig;
                uint32_t b0 = ldh2(bp), b1 = ldh2(bp + 8);
                mma_f16(acc[0][nt], af[0], b0, b1);
                mma_f16(acc[1][nt], af[1], b0, b1);
            }
        }
    }
    __syncthreads();

    if (z < 2) {
        __half* Y = (z == 0) ? g_Qh : g_Kh;
#pragma unroll
        for (int mt = 0; mt < 2; mt++) {
            const int r = m0 + wm * 32 + mt * 16 + g;
#pragma unroll
            for (int nt = 0; nt < 8; nt++) {
                const int c = n0 + wn * 64 + nt * 8 + 2 * tig;
                const float b0 = bias[c], b1 = bias[c + 1];
                *reinterpret_cast<__half2*>(&Y[(size_t)r * HID + c]) =
                    __floats2half2_rn(acc[mt][nt][0] + b0, acc[mt][nt][1] + b1);
                *reinterpret_cast<__half2*>(&Y[(size_t)(r + 8) * HID + c]) =
                    __floats2half2_rn(acc[mt][nt][2] + b0, acc[mt][nt][3] + b1);
            }
        }
    } else {
        // V: transpose through SMEM, then coalesced stores to g_Vt[(b,h,hd)][s]
        __half* sT = reinterpret_cast<__half*>(smq);   // [128 cols][136] stride
#pragma unroll
        for (int mt = 0; mt < 2; mt++) {
            const int rl = wm * 32 + mt * 16 + g;
#pragma unroll
            for (int nt = 0; nt < 8; nt++) {
                const int cl = wn * 64 + nt * 8 + 2 * tig;
                const float b0 = bias[n0 + cl], b1 = bias[n0 + cl + 1];
                sT[cl * 136 + rl]           = __float2half(acc[mt][nt][0] + b0);
                sT[(cl + 1) * 136 + rl]     = __float2half(acc[mt][nt][1] + b1);
                sT[cl * 136 + rl + 8]       = __float2half(acc[mt][nt][2] + b0);
                sT[(cl + 1) * 136 + rl + 8] = __float2half(acc[mt][nt][3] + b1);
            }
        }
        __syncthreads();
        const int bb = m0 >> 11;
        const int s0 = m0 & 2047;
#pragma unroll
        for (int j = 0; j < 8; j++) {
            int id = tid + j * 256;       // 2048 chunks of 16B
            int cl = id >> 4, ch = id & 15;
            int c = n0 + cl;
            int hh = c >> 6, hd = c & 63;
            *reinterpret_cast<uint4*>(
                g_Vt + ((size_t)(bb * NH + hh) * HD + hd) * S_LEN + s0 + ch * 8) =
                *reinterpret_cast<const uint4*>(sT + cl * 136 + ch * 8);
        }
    }
}

// ============================================================================
// Kernel 2: attention.  fp16 mma, 3-stage cp.async, single sync per tile,
// register-resident Q and P.  256 thr, 8 warps = 4(m) x 2(n).
// (round-14 proven base; sweep-1 exp now via ex2.approx.f16x2)
// ============================================================================
#define SKW 72    // K tile stride (halves): 128 rows x 64 hd
#define SVW 136   // Vt tile stride (halves): 64 hd rows x 128 s
#define SZK (128 * SKW * 2)     // 18432
#define SZV (64 * SVW * 2)      // 17408
#define OFF_KB(i) ((i) * SZK)
#define OFF_VB(i) (3 * SZK + (i) * SZV)
#define OFF_SL    (3 * SZK + 3 * SZV)
#define ATTN_SMEM (OFF_SL + 512)    // 108032

__device__ __forceinline__ void load_k_tile(uint32_t sbase, const __half* Kg,
                                            int k0, int tid) {
#pragma unroll
    for (int j = 0; j < 4; j++) {
        int id = tid + j * 256;
        int r = id >> 3, ch = id & 7;
        cp16(sbase + (uint32_t)(r * SKW + ch * 8) * 2,
             Kg + (size_t)(k0 + r) * HID + ch * 8);
    }
}
__device__ __forceinline__ void load_v_tile(uint32_t sbase, const __half* Vt,
                                            int k0, int tid) {
#pragma unroll
    for (int j = 0; j < 4; j++) {
        int id = tid + j * 256;
        int hd = id >> 4, ch = id & 15;
        cp16(sbase + (uint32_t)(hd * SVW + ch * 8) * 2,
             Vt + (size_t)hd * S_LEN + k0 + ch * 8);
    }
}

__global__ __launch_bounds__(256, 1) void attn_kernel(
    float* __restrict__ ctx_out, float* __restrict__ probs_out)
{
    extern __shared__ char sm[];
    const uint32_t smb = (uint32_t)__cvta_generic_to_shared(sm);
    const int tid = threadIdx.x, wid = tid >> 5, lane = tid & 31;
    const int g = lane >> 2, tig = lane & 3;
    const int wm = wid & 3, wn = wid >> 2;
    const int q0 = blockIdx.x * 128, h = blockIdx.y, b = blockIdx.z;

    const __half* Qg = g_Qh + (size_t)b * S_LEN * HID + (size_t)h * HD;
    const __half* Kg = g_Kh + (size_t)b * S_LEN * HID + (size_t)h * HD;
    const __half* Vt = g_Vt + (size_t)(b * NH + h) * HD * S_LEN;
    float* sL = reinterpret_cast<float*>(sm + OFF_SL);

    // Q fragments: register-resident for the whole kernel
    uint32_t qf[4][2][4];
#pragma unroll
    for (int ks = 0; ks < 4; ks++)
#pragma unroll
        for (int mt = 0; mt < 2; mt++) {
            const __half* qp = Qg + (size_t)(q0 + wm * 32 + mt * 16 + g) * HID
                               + ks * 16 + 2 * tig;
            qf[ks][mt][0] = ldh2(qp);
            qf[ks][mt][1] = ldh2(qp + 8 * HID);
            qf[ks][mt][2] = ldh2(qp + 8);
            qf[ks][mt][3] = ldh2(qp + 8 * HID + 8);
        }

    if (tid < 128) sL[tid] = 0.f;
    __syncthreads();

    // ---------------- sweep 1: denominators ----------------
    load_k_tile(smb + OFF_KB(0), Kg, 0, tid); cp_commit();
    load_k_tile(smb + OFF_KB(1), Kg, 128, tid); cp_commit();
    float rs[4] = {0.f, 0.f, 0.f, 0.f};

    for (int kt = 0; kt < 16; kt++) {
        if (kt < 15) cp_wait1(); else cp_wait0();
        __syncthreads();
        if (kt + 2 < 16) {
            load_k_tile(smb + OFF_KB((kt + 2) % 3), Kg, (kt + 2) * 128, tid);
            cp_commit();
        }
        const __half* sK = reinterpret_cast<const __half*>(sm + OFF_KB(kt % 3));
        float accS[2][8][4];
#pragma unroll
        for (int i = 0; i < 2; i++)
#pragma unroll
            for (int j = 0; j < 8; j++)
#pragma unroll
                for (int k = 0; k < 4; k++) accS[i][j][k] = 0.f;
#pragma unroll
        for (int ks = 0; ks < 4; ks++)
#pragma unroll
            for (int nt = 0; nt < 8; nt++) {
                const __half* bp = sK + (wn * 64 + nt * 8 + g) * SKW + ks * 16 + 2 * tig;
                uint32_t b0 = ldh2(bp), b1 = ldh2(bp + 8);
                mma_f16(accS[0][nt], qf[ks][0], b0, b1);
                mma_f16(accS[1][nt], qf[ks][1], b0, b1);
            }
        // rowsums via f16x2 ex2: 2 exps per MUFU op, fp32 accumulation
#pragma unroll
        for (int mt = 0; mt < 2; mt++)
#pragma unroll
            for (int nt = 0; nt < 8; nt++) {
                uint32_t ea = h2ex2(pack2(accS[mt][nt][0] * EXPC,
                                          accS[mt][nt][1] * EXPC));
                uint32_t eb = h2ex2(pack2(accS[mt][nt][2] * EXPC,
                                          accS[mt][nt][3] * EXPC));
                float2 fa = __half22float2(*reinterpret_cast<__half2*>(&ea));
                float2 fb = __half22float2(*reinterpret_cast<__half2*>(&eb));
                rs[mt * 2]     += fa.x + fa.y;
                rs[mt * 2 + 1] += fb.x + fb.y;
            }
    }
#pragma unroll
    for (int o = 1; o < 4; o <<= 1)
#pragma unroll
        for (int j = 0; j < 4; j++) rs[j] += __shfl_xor_sync(0xffffffffu, rs[j], o);
    __syncthreads();          // all warps done with K buffers + sL zeroed visible
    if (tig == 0) {
        atomicAdd(&sL[wm * 32      + g], rs[0]);
        atomicAdd(&sL[wm * 32 + 8  + g], rs[1]);
        atomicAdd(&sL[wm * 32 + 16 + g], rs[2]);
        atomicAdd(&sL[wm * 32 + 24 + g], rs[3]);
    }
    __syncthreads();
    float rinv[4];
#pragma unroll
    for (int j = 0; j < 4; j++) rinv[j] = 1.0f / sL[wm * 32 + j * 8 + g];
    __syncthreads();

    // ---------------- sweep 2: probs + ctx ----------------
    load_k_tile(smb + OFF_KB(0), Kg, 0, tid);
    load_v_tile(smb + OFF_VB(0), Vt, 0, tid);
    cp_commit();
    load_k_tile(smb + OFF_KB(1), Kg, 128, tid);
    load_v_tile(smb + OFF_VB(1), Vt, 128, tid);
    cp_commit();

    float accO[2][8][4];
#pragma unroll
    for (int i = 0; i < 2; i++)
#pragma unroll
        for (int j = 0; j < 8; j++)
#pragma unroll
            for (int k = 0; k < 4; k++) accO[i][j][k] = 0.f;

    const size_t pb = ((size_t)(b * NH + h) * S_LEN + q0) * S_LEN;

    for (int kt = 0; kt < 16; kt++) {
        if (kt < 15) cp_wait1(); else cp_wait0();
        __syncthreads();
        if (kt + 2 < 16) {
            load_k_tile(smb + OFF_KB((kt + 2) % 3), Kg, (kt + 2) * 128, tid);
            load_v_tile(smb + OFF_VB((kt + 2) % 3), Vt, (kt + 2) * 128, tid);
            cp_commit();
        }
        const __half* sK  = reinterpret_cast<const __half*>(sm + OFF_KB(kt % 3));
        const __half* sVt = reinterpret_cast<const __half*>(sm + OFF_VB(kt % 3));

        float accS[2][8][4];
#pragma unroll
        for (int i = 0; i < 2; i++)
#pragma unroll
            for (int j = 0; j < 8; j++)
#pragma unroll
                for (int k = 0; k < 4; k++) accS[i][j][k] = 0.f;
#pragma unroll
        for (int ks = 0; ks < 4; ks++)
#pragma unroll
            for (int nt = 0; nt < 8; nt++) {
                const __half* bp = sK + (wn * 64 + nt * 8 + g) * SKW + ks * 16 + 2 * tig;
                uint32_t b0 = ldh2(bp), b1 = ldh2(bp + 8);
                mma_f16(accS[0][nt], qf[ks][0], b0, b1);
                mma_f16(accS[1][nt], qf[ks][1], b0, b1);
            }

        // exp + normalize, streaming-store probs, keep p in accS (fp32 exp here)
#pragma unroll
        for (int mt = 0; mt < 2; mt++) {
            const int r0 = wm * 32 + mt * 16 + g;
#pragma unroll
            for (int nt = 0; nt < 8; nt++) {
                float p0 = fexp2(accS[mt][nt][0] * EXPC) * rinv[mt * 2];
                float p1 = fexp2(accS[mt][nt][1] * EXPC) * rinv[mt * 2];
                float p2 = fexp2(accS[mt][nt][2] * EXPC) * rinv[mt * 2 + 1];
                float p3 = fexp2(accS[mt][nt][3] * EXPC) * rinv[mt * 2 + 1];
                accS[mt][nt][0] = p0; accS[mt][nt][1] = p1;
                accS[mt][nt][2] = p2; accS[mt][nt][3] = p3;
                const size_t cidx = (size_t)kt * 128 + wn * 64 + nt * 8 + 2 * tig;
                stg_cs2(probs_out + pb + (size_t)r0 * S_LEN + cidx, p0, p1);
                stg_cs2(probs_out + pb + (size_t)(r0 + 8) * S_LEN + cidx, p2, p3);
            }
        }

        // pack P into fp16 A-fragments (register-only)
        uint32_t ph[2][4][4];
#pragma unroll
        for (int mt = 0; mt < 2; mt++)
#pragma unroll
            for (int j = 0; j < 4; j++) {
                ph[mt][j][0] = pack2(accS[mt][2 * j][0],     accS[mt][2 * j][1]);
                ph[mt][j][1] = pack2(accS[mt][2 * j][2],     accS[mt][2 * j][3]);
                ph[mt][j][2] = pack2(accS[mt][2 * j + 1][0], accS[mt][2 * j + 1][1]);
                ph[mt][j][3] = pack2(accS[mt][2 * j + 1][2], accS[mt][2 * j + 1][3]);
            }

        // O += P * V  (this warp's 64-k slice; partial over wn)
#pragma unroll
        for (int j = 0; j < 4; j++)
#pragma unroll
            for (int nt = 0; nt < 8; nt++) {
                const __half* vp = sVt + (nt * 8 + g) * SVW + wn * 64 + j * 16 + 2 * tig;
                uint32_t b0 = ldh2(vp), b1 = ldh2(vp + 8);
                mma_f16(accO[0][nt], ph[0][j], b0, b1);
                mma_f16(accO[1][nt], ph[1][j], b0, b1);
            }
    }
    __syncthreads();   // K/V buffers dead; reuse base of smem for O reduction

    // ---------------- O reduction across wn halves + ctx write ----------------
    float* sRed = reinterpret_cast<float*>(sm);   // [128][68]
    if (wn == 0) {
#pragma unroll
        for (int mt = 0; mt < 2; mt++) {
            const int r = wm * 32 + mt * 16 + g;
#pragma unroll
            for (int nt = 0; nt < 8; nt++) {
                const int c = nt * 8 + 2 * tig;
                *reinterpret_cast<float2*>(&sRed[r * 68 + c]) =
                    make_float2(accO[mt][nt][0], accO[mt][nt][1]);
                *reinterpret_cast<float2*>(&sRed[(r + 8) * 68 + c]) =
                    make_float2(accO[mt][nt][2], accO[mt][nt][3]);
            }
        }
    }
    __syncthreads();
    if (wn == 1) {
#pragma unroll
        for (int mt = 0; mt < 2; mt++) {
            const int r = wm * 32 + mt * 16 + g;
#pragma unroll
            for (int nt = 0; nt < 8; nt++) {
                const int c = nt * 8 + 2 * tig;
                float2 a = *reinterpret_cast<float2*>(&sRed[r * 68 + c]);
                *reinterpret_cast<float2*>(&sRed[r * 68 + c]) =
                    make_float2(a.x + accO[mt][nt][0], a.y + accO[mt][nt][1]);
                float2 d = *reinterpret_cast<float2*>(&sRed[(r + 8) * 68 + c]);
                *reinterpret_cast<float2*>(&sRed[(r + 8) * 68 + c]) =
                    make_float2(d.x + accO[mt][nt][2], d.y + accO[mt][nt][3]);
            }
        }
    }
    __syncthreads();
    {
        const int row = tid >> 1, cb = (tid & 1) * 32;
        float* cw = ctx_out + (size_t)(b * S_LEN + q0 + row) * HID + h * HD + cb;
        const float* rr = sRed + row * 68 + cb;
#pragma unroll
        for (int i = 0; i < 8; i++)
            *reinterpret_cast<float4*>(cw + 4 * i) =
                *reinterpret_cast<const float4*>(rr + 4 * i);
    }
}

// ============================================================================
// launch
// ============================================================================
extern "C" void kernel_launch(void* const* d_in, const int* in_sizes, int n_in,
                              void* d_out, int out_size)
{
    const float* X  = (const float*)d_in[0];
    const float* Wq = (const float*)d_in[1];
    const float* bq = (const float*)d_in[2];
    const float* Wk = (const float*)d_in[3];
    const float* bk = (const float*)d_in[4];
    const float* Wv = (const float*)d_in[5];
    const float* bv = (const float*)d_in[6];

    float* ctx   = (float*)d_out;                         // [2,2048,1024]
    float* probs = ctx + (size_t)BATCH * S_LEN * HID;     // [2,16,2048,2048]

    cvt_kernel<<<(unsigned)((NCVT + 255) / 256), 256>>>(X, Wq, Wk, Wv);

    cudaFuncSetAttribute(qkv_kernel, cudaFuncAttributeMaxDynamicSharedMemorySize,
                         QKV_SMEM);
    qkv_kernel<<<dim3(HID / 128, M_TOT / 128, 3), 256, QKV_SMEM>>>(bq, bk, bv);

    cudaFuncSetAttribute(attn_kernel, cudaFuncAttributeMaxDynamicSharedMemorySize,
                         ATTN_SMEM);
    attn_kernel<<<dim3(S_LEN / 128, NH, BATCH), 256, ATTN_SMEM>>>(ctx, probs);
}

// round 17
// speedup vs baseline: 1.0735x; 1.0240x over previous
#include <cuda_runtime.h>
#include <cuda_fp16.h>
#include <cstdint>
#include <cstddef>

#define S_LEN 2048
#define HID   1024
#define NH    16
#define HD    64
#define BATCH 2
#define M_TOT (BATCH * S_LEN)   // 4096

// ---------------- scratch (static device arrays; no allocation) -------------
__device__ __half g_Xh[(size_t)M_TOT * HID];
__device__ __half g_Wh[3ull * HID * HID];
__device__ __half g_Qh[(size_t)M_TOT * HID];
__device__ __half g_Kh[(size_t)M_TOT * HID];
__device__ __half g_Vt[(size_t)BATCH * NH * HD * S_LEN];  // [(b*NH+h)*HD+hd][s]

// ---------------- helpers ---------------------------------------------------
__device__ __forceinline__ void mma_f16(float d[4], const uint32_t a[4],
                                        uint32_t b0, uint32_t b1) {
    asm volatile(
        "mma.sync.aligned.m16n8k16.row.col.f32.f16.f16.f32 "
        "{%0,%1,%2,%3}, {%4,%5,%6,%7}, {%8,%9}, {%0,%1,%2,%3};\n"
        : "+f"(d[0]), "+f"(d[1]), "+f"(d[2]), "+f"(d[3])
        : "r"(a[0]), "r"(a[1]), "r"(a[2]), "r"(a[3]), "r"(b0), "r"(b1));
}
__device__ __forceinline__ uint32_t pack2(float lo, float hi) {
    __half2 h = __floats2half2_rn(lo, hi);
    return *reinterpret_cast<uint32_t*>(&h);
}
__device__ __forceinline__ uint32_t ldh2(const __half* p) {
    return *reinterpret_cast<const uint32_t*>(p);
}
// exp(s/8) = ex2(s * log2(e)/8); folded constant, one FMUL + MUFU.EX2
#define EXPC 0.18033688f
__device__ __forceinline__ float fexp2(float x) {
    float r;
    asm("ex2.approx.ftz.f32 %0, %1;" : "=f"(r) : "f"(x));
    return r;
}
// streaming store for probs (write-once, never re-read): evict-first in L2
__device__ __forceinline__ void stg_cs2(float* p, float x, float y) {
    asm volatile("st.global.cs.v2.f32 [%0], {%1, %2};" :: "l"(p), "f"(x), "f"(y)
                 : "memory");
}
__device__ __forceinline__ void cp16(uint32_t dst, const void* src) {
    asm volatile("cp.async.cg.shared.global [%0], [%1], 16;" :: "r"(dst), "l"(src));
}
__device__ __forceinline__ void cp_commit() {
    asm volatile("cp.async.commit_group;");
}
__device__ __forceinline__ void cp_wait1() { asm volatile("cp.async.wait_group 1;"); }
__device__ __forceinline__ void cp_wait0() { asm volatile("cp.async.wait_group 0;"); }

// ============================================================================
// Kernel 0: fp32 -> fp16 conversion of X, Wq, Wk, Wv
// ============================================================================
#define NX4 ((size_t)M_TOT * HID / 4)        // 1048576
#define NW4 ((size_t)HID * HID / 4)          // 262144
#define NCVT (NX4 + 3 * NW4)

__global__ __launch_bounds__(256) void cvt_kernel(
    const float* __restrict__ X, const float* __restrict__ Wq,
    const float* __restrict__ Wk, const float* __restrict__ Wv)
{
    size_t i = (size_t)blockIdx.x * blockDim.x + threadIdx.x;
    if (i >= NCVT) return;
    const float* src; __half* dst; size_t j;
    if (i < NX4)                { src = X;  dst = g_Xh;            j = i; }
    else if (i < NX4 + NW4)     { src = Wq; dst = g_Wh;            j = i - NX4; }
    else if (i < NX4 + 2 * NW4) { src = Wk; dst = g_Wh + NW4 * 4;  j = i - NX4 - NW4; }
    else                        { src = Wv; dst = g_Wh + NW4 * 8;  j = i - NX4 - 2 * NW4; }
    float4 v = *reinterpret_cast<const float4*>(src + 4 * j);
    __half2 h0 = __floats2half2_rn(v.x, v.y);
    __half2 h1 = __floats2half2_rn(v.z, v.w);
    uint2 out = { *reinterpret_cast<uint32_t*>(&h0), *reinterpret_cast<uint32_t*>(&h1) };
    *reinterpret_cast<uint2*>(dst + 4 * j) = out;
}

// ============================================================================
// Kernel 1: QKV projection.  fp16 cp.async GEMM, CTA 128x128, BK=64, 256 thr,
// 8 warps 4(m) x 2(n), 3-stage single-sync pipeline.  (round-14 proven)
// ============================================================================
#define QSTR 72                               // smem row stride in halves
#define QSZ  (128 * QSTR * 2)                 // 18432 B per tile
#define QSA(i) ((i) * QSZ)
#define QSB(i) (3 * QSZ + (i) * QSZ)
#define QKV_SMEM (6 * QSZ)                    // 110592 B

__device__ __forceinline__ void qkv_load(uint32_t sbase, const __half* g,
                                         int row0, int kt, int tid) {
#pragma unroll
    for (int j = 0; j < 4; j++) {
        int id = tid + j * 256;               // 1024 chunks of 16B
        int r = id >> 3, ch = id & 7;
        cp16(sbase + (uint32_t)(r * QSTR + ch * 8) * 2,
             g + (size_t)(row0 + r) * HID + kt * 64 + ch * 8);
    }
}

__global__ __launch_bounds__(256, 1) void qkv_kernel(
    const float* __restrict__ bq, const float* __restrict__ bk,
    const float* __restrict__ bv)
{
    extern __shared__ char smq[];
    const uint32_t smb = (uint32_t)__cvta_generic_to_shared(smq);
    const int z = blockIdx.z;
    const __half* A = g_Xh;
    const __half* Bm = g_Wh + (size_t)z * HID * HID;
    const float* bias = (z == 0) ? bq : (z == 1) ? bk : bv;

    const int tid = threadIdx.x, wid = tid >> 5, lane = tid & 31;
    const int g = lane >> 2, tig = lane & 3;
    const int wm = wid & 3, wn = wid >> 2;
    const int m0 = blockIdx.y * 128, n0 = blockIdx.x * 128;

    float acc[2][8][4];
#pragma unroll
    for (int i = 0; i < 2; i++)
#pragma unroll
        for (int j = 0; j < 8; j++)
#pragma unroll
            for (int k = 0; k < 4; k++) acc[i][j][k] = 0.f;

    qkv_load(smb + QSA(0), A, m0, 0, tid);
    qkv_load(smb + QSB(0), Bm, n0, 0, tid);
    cp_commit();
    qkv_load(smb + QSA(1), A, m0, 1, tid);
    qkv_load(smb + QSB(1), Bm, n0, 1, tid);
    cp_commit();

    for (int kt = 0; kt < 16; kt++) {
        if (kt < 15) cp_wait1(); else cp_wait0();
        __syncthreads();
        if (kt + 2 < 16) {
            const int s = (kt + 2) % 3;
            qkv_load(smb + QSA(s), A, m0, kt + 2, tid);
            qkv_load(smb + QSB(s), Bm, n0, kt + 2, tid);
            cp_commit();
        }
        const __half* sA = reinterpret_cast<const __half*>(smq + QSA(kt % 3));
        const __half* sB = reinterpret_cast<const __half*>(smq + QSB(kt % 3));
#pragma unroll
        for (int ks = 0; ks < 4; ks++) {
            const int kb = ks * 16;
            uint32_t af[2][4];
#pragma unroll
            for (int mt = 0; mt < 2; mt++) {
                const __half* ap = sA + (wm * 32 + mt * 16 + g) * QSTR + kb + 2 * tig;
                af[mt][0] = ldh2(ap);
                af[mt][1] = ldh2(ap + 8 * QSTR);
                af[mt][2] = ldh2(ap + 8);
                af[mt][3] = ldh2(ap + 8 * QSTR + 8);
            }
#pragma unroll
            for (int nt = 0; nt < 8; nt++) {
                const __half* bp = sB + (wn * 64 + nt * 8 + g) * QSTR + kb + 2 * tig;
                uint32_t b0 = ldh2(bp), b1 = ldh2(bp + 8);
                mma_f16(acc[0][nt], af[0], b0, b1);
                mma_f16(acc[1][nt], af[1], b0, b1);
            }
        }
    }
    __syncthreads();

    if (z < 2) {
        __half* Y = (z == 0) ? g_Qh : g_Kh;
#pragma unroll
        for (int mt = 0; mt < 2; mt++) {
            const int r = m0 + wm * 32 + mt * 16 + g;
#pragma unroll
            for (int nt = 0; nt < 8; nt++) {
                const int c = n0 + wn * 64 + nt * 8 + 2 * tig;
                const float b0 = bias[c], b1 = bias[c + 1];
                *reinterpret_cast<__half2*>(&Y[(size_t)r * HID + c]) =
                    __floats2half2_rn(acc[mt][nt][0] + b0, acc[mt][nt][1] + b1);
                *reinterpret_cast<__half2*>(&Y[(size_t)(r + 8) * HID + c]) =
                    __floats2half2_rn(acc[mt][nt][2] + b0, acc[mt][nt][3] + b1);
            }
        }
    } else {
        // V: transpose through SMEM, then coalesced stores to g_Vt[(b,h,hd)][s]
        __half* sT = reinterpret_cast<__half*>(smq);   // [128 cols][136] stride
#pragma unroll
        for (int mt = 0; mt < 2; mt++) {
            const int rl = wm * 32 + mt * 16 + g;
#pragma unroll
            for (int nt = 0; nt < 8; nt++) {
                const int cl = wn * 64 + nt * 8 + 2 * tig;
                const float b0 = bias[n0 + cl], b1 = bias[n0 + cl + 1];
                sT[cl * 136 + rl]           = __float2half(acc[mt][nt][0] + b0);
                sT[(cl + 1) * 136 + rl]     = __float2half(acc[mt][nt][1] + b1);
                sT[cl * 136 + rl + 8]       = __float2half(acc[mt][nt][2] + b0);
                sT[(cl + 1) * 136 + rl + 8] = __float2half(acc[mt][nt][3] + b1);
            }
        }
        __syncthreads();
        const int bb = m0 >> 11;
        const int s0 = m0 & 2047;
#pragma unroll
        for (int j = 0; j < 8; j++) {
            int id = tid + j * 256;       // 2048 chunks of 16B
            int cl = id >> 4, ch = id & 15;
            int c = n0 + cl;
            int hh = c >> 6, hd = c & 63;
            *reinterpret_cast<uint4*>(
                g_Vt + ((size_t)(bb * NH + hh) * HD + hd) * S_LEN + s0 + ch * 8) =
                *reinterpret_cast<const uint4*>(sT + cl * 136 + ch * 8);
        }
    }
}

// ============================================================================
// Kernel 2: attention.  fp16 mma, 256-wide K/V tiles processed as 2x128
// halves per barrier (8 barriers/sweep instead of 16), 3-stage cp.async,
// register-resident Q and P, .cs probs stores.  256 thr, 8 warps 4(m)x2(n).
// ============================================================================
#define SKW 72     // K tile stride (halves): 256 rows x 64 hd
#define SVW 264    // Vt tile stride (halves): 64 hd rows x 256 s
#define SZK (256 * SKW * 2)     // 36864
#define SZV (64 * SVW * 2)      // 33792
#define OFF_KB(i) ((i) * SZK)
#define OFF_VB(i) (3 * SZK + (i) * SZV)
#define OFF_SL    (3 * SZK + 3 * SZV)        // 211968
#define ATTN_SMEM (OFF_SL + 512)             // 212480 <= 227KB cap

__device__ __forceinline__ void load_k_tile(uint32_t sbase, const __half* Kg,
                                            int k0, int tid) {
#pragma unroll
    for (int j = 0; j < 8; j++) {
        int id = tid + j * 256;        // 2048 chunks of 16B (256 rows x 64 hd)
        int r = id >> 3, ch = id & 7;
        cp16(sbase + (uint32_t)(r * SKW + ch * 8) * 2,
             Kg + (size_t)(k0 + r) * HID + ch * 8);
    }
}
__device__ __forceinline__ void load_v_tile(uint32_t sbase, const __half* Vt,
                                            int k0, int tid) {
#pragma unroll
    for (int j = 0; j < 8; j++) {
        int id = tid + j * 256;        // 2048 chunks of 16B (64 hd x 256 s)
        int hd = id >> 5, ch = id & 31;
        cp16(sbase + (uint32_t)(hd * SVW + ch * 8) * 2,
             Vt + (size_t)hd * S_LEN + k0 + ch * 8);
    }
}

__global__ __launch_bounds__(256, 1) void attn_kernel(
    float* __restrict__ ctx_out, float* __restrict__ probs_out)
{
    extern __shared__ char sm[];
    const uint32_t smb = (uint32_t)__cvta_generic_to_shared(sm);
    const int tid = threadIdx.x, wid = tid >> 5, lane = tid & 31;
    const int g = lane >> 2, tig = lane & 3;
    const int wm = wid & 3, wn = wid >> 2;
    const int q0 = blockIdx.x * 128, h = blockIdx.y, b = blockIdx.z;

    const __half* Qg = g_Qh + (size_t)b * S_LEN * HID + (size_t)h * HD;
    const __half* Kg = g_Kh + (size_t)b * S_LEN * HID + (size_t)h * HD;
    const __half* Vt = g_Vt + (size_t)(b * NH + h) * HD * S_LEN;
    float* sL = reinterpret_cast<float*>(sm + OFF_SL);

    // Q fragments: register-resident for the whole kernel
    uint32_t qf[4][2][4];
#pragma unroll
    for (int ks = 0; ks < 4; ks++)
#pragma unroll
        for (int mt = 0; mt < 2; mt++) {
            const __half* qp = Qg + (size_t)(q0 + wm * 32 + mt * 16 + g) * HID
                               + ks * 16 + 2 * tig;
            qf[ks][mt][0] = ldh2(qp);
            qf[ks][mt][1] = ldh2(qp + 8 * HID);
            qf[ks][mt][2] = ldh2(qp + 8);
            qf[ks][mt][3] = ldh2(qp + 8 * HID + 8);
        }

    if (tid < 128) sL[tid] = 0.f;
    __syncthreads();

    // ---------------- sweep 1: denominators ----------------
    load_k_tile(smb + OFF_KB(0), Kg, 0, tid); cp_commit();
    load_k_tile(smb + OFF_KB(1), Kg, 256, tid); cp_commit();
    float rs[4] = {0.f, 0.f, 0.f, 0.f};

    for (int kt = 0; kt < 8; kt++) {
        if (kt < 7) cp_wait1(); else cp_wait0();
        __syncthreads();
        if (kt + 2 < 8) {
            load_k_tile(smb + OFF_KB((kt + 2) % 3), Kg, (kt + 2) * 256, tid);
            cp_commit();
        }
#pragma unroll
        for (int half = 0; half < 2; half++) {
            const __half* sK = reinterpret_cast<const __half*>(sm + OFF_KB(kt % 3))
                               + half * 128 * SKW;
            float accS[2][8][4];
#pragma unroll
            for (int i = 0; i < 2; i++)
#pragma unroll
                for (int j = 0; j < 8; j++)
#pragma unroll
                    for (int k = 0; k < 4; k++) accS[i][j][k] = 0.f;
#pragma unroll
            for (int ks = 0; ks < 4; ks++)
#pragma unroll
                for (int nt = 0; nt < 8; nt++) {
                    const __half* bp = sK + (wn * 64 + nt * 8 + g) * SKW + ks * 16 + 2 * tig;
                    uint32_t b0 = ldh2(bp), b1 = ldh2(bp + 8);
                    mma_f16(accS[0][nt], qf[ks][0], b0, b1);
                    mma_f16(accS[1][nt], qf[ks][1], b0, b1);
                }
#pragma unroll
            for (int mt = 0; mt < 2; mt++)
#pragma unroll
                for (int nt = 0; nt < 8; nt++) {
                    rs[mt * 2]     += fexp2(accS[mt][nt][0] * EXPC) + fexp2(accS[mt][nt][1] * EXPC);
                    rs[mt * 2 + 1] += fexp2(accS[mt][nt][2] * EXPC) + fexp2(accS[mt][nt][3] * EXPC);
                }
        }
    }
#pragma unroll
    for (int o = 1; o < 4; o <<= 1)
#pragma unroll
        for (int j = 0; j < 4; j++) rs[j] += __shfl_xor_sync(0xffffffffu, rs[j], o);
    __syncthreads();          // all warps done with K buffers + sL zeroed visible
    if (tig == 0) {
        atomicAdd(&sL[wm * 32      + g], rs[0]);
        atomicAdd(&sL[wm * 32 + 8  + g], rs[1]);
        atomicAdd(&sL[wm * 32 + 16 + g], rs[2]);
        atomicAdd(&sL[wm * 32 + 24 + g], rs[3]);
    }
    __syncthreads();
    float rinv[4];
#pragma unroll
    for (int j = 0; j < 4; j++) rinv[j] = 1.0f / sL[wm * 32 + j * 8 + g];
    __syncthreads();

    // ---------------- sweep 2: probs + ctx ----------------
    load_k_tile(smb + OFF_KB(0), Kg, 0, tid);
    load_v_tile(smb + OFF_VB(0), Vt, 0, tid);
    cp_commit();
    load_k_tile(smb + OFF_KB(1), Kg, 256, tid);
    load_v_tile(smb + OFF_VB(1), Vt, 256, tid);
    cp_commit();

    float accO[2][8][4];
#pragma unroll
    for (int i = 0; i < 2; i++)
#pragma unroll
        for (int j = 0; j < 8; j++)
#pragma unroll
            for (int k = 0; k < 4; k++) accO[i][j][k] = 0.f;

    const size_t pb = ((size_t)(b * NH + h) * S_LEN + q0) * S_LEN;

    for (int kt = 0; kt < 8; kt++) {
        if (kt < 7) cp_wait1(); else cp_wait0();
        __syncthreads();
        if (kt + 2 < 8) {
            load_k_tile(smb + OFF_KB((kt + 2) % 3), Kg, (kt + 2) * 256, tid);
            load_v_tile(smb + OFF_VB((kt + 2) % 3), Vt, (kt + 2) * 256, tid);
            cp_commit();
        }
#pragma unroll
        for (int half = 0; half < 2; half++) {
            const __half* sK  = reinterpret_cast<const __half*>(sm + OFF_KB(kt % 3))
                                + half * 128 * SKW;
            const __half* sVt = reinterpret_cast<const __half*>(sm + OFF_VB(kt % 3))
                                + half * 128;

            float accS[2][8][4];
#pragma unroll
            for (int i = 0; i < 2; i++)
#pragma unroll
                for (int j = 0; j < 8; j++)
#pragma unroll
                    for (int k = 0; k < 4; k++) accS[i][j][k] = 0.f;
#pragma unroll
            for (int ks = 0; ks < 4; ks++)
#pragma unroll
                for (int nt = 0; nt < 8; nt++) {
                    const __half* bp = sK + (wn * 64 + nt * 8 + g) * SKW + ks * 16 + 2 * tig;
                    uint32_t b0 = ldh2(bp), b1 = ldh2(bp + 8);
                    mma_f16(accS[0][nt], qf[ks][0], b0, b1);
                    mma_f16(accS[1][nt], qf[ks][1], b0, b1);
                }

            // exp + normalize, streaming-store probs, keep p in accS
#pragma unroll
            for (int mt = 0; mt < 2; mt++) {
                const int r0 = wm * 32 + mt * 16 + g;
#pragma unroll
                for (int nt = 0; nt < 8; nt++) {
                    float p0 = fexp2(accS[mt][nt][0] * EXPC) * rinv[mt * 2];
                    float p1 = fexp2(accS[mt][nt][1] * EXPC) * rinv[mt * 2];
                    float p2 = fexp2(accS[mt][nt][2] * EXPC) * rinv[mt * 2 + 1];
                    float p3 = fexp2(accS[mt][nt][3] * EXPC) * rinv[mt * 2 + 1];
                    accS[mt][nt][0] = p0; accS[mt][nt][1] = p1;
                    accS[mt][nt][2] = p2; accS[mt][nt][3] = p3;
                    const size_t cidx = (size_t)kt * 256 + half * 128
                                        + wn * 64 + nt * 8 + 2 * tig;
                    stg_cs2(probs_out + pb + (size_t)r0 * S_LEN + cidx, p0, p1);
                    stg_cs2(probs_out + pb + (size_t)(r0 + 8) * S_LEN + cidx, p2, p3);
                }
            }

            // pack P into fp16 A-fragments (register-only)
            uint32_t ph[2][4][4];
#pragma unroll
            for (int mt = 0; mt < 2; mt++)
#pragma unroll
                for (int j = 0; j < 4; j++) {
                    ph[mt][j][0] = pack2(accS[mt][2 * j][0],     accS[mt][2 * j][1]);
                    ph[mt][j][1] = pack2(accS[mt][2 * j][2],     accS[mt][2 * j][3]);
                    ph[mt][j][2] = pack2(accS[mt][2 * j + 1][0], accS[mt][2 * j + 1][1]);
                    ph[mt][j][3] = pack2(accS[mt][2 * j + 1][2], accS[mt][2 * j + 1][3]);
                }

            // O += P * V  (this warp's 64-k slice within this half)
#pragma unroll
            for (int j = 0; j < 4; j++)
#pragma unroll
                for (int nt = 0; nt < 8; nt++) {
                    const __half* vp = sVt + (nt * 8 + g) * SVW + wn * 64 + j * 16 + 2 * tig;
                    uint32_t b0 = ldh2(vp), b1 = ldh2(vp + 8);
                    mma_f16(accO[0][nt], ph[0][j], b0, b1);
                    mma_f16(accO[1][nt], ph[1][j], b0, b1);
                }
        }
    }
    __syncthreads();   // K/V buffers dead; reuse base of smem for O reduction

    // ---------------- O reduction across wn halves + ctx write ----------------
    float* sRed = reinterpret_cast<float*>(sm);   // [128][68]
    if (wn == 0) {
#pragma unroll
        for (int mt = 0; mt < 2; mt++) {
            const int r = wm * 32 + mt * 16 + g;
#pragma unroll
            for (int nt = 0; nt < 8; nt++) {
                const int c = nt * 8 + 2 * tig;
                *reinterpret_cast<float2*>(&sRed[r * 68 + c]) =
                    make_float2(accO[mt][nt][0], accO[mt][nt][1]);
                *reinterpret_cast<float2*>(&sRed[(r + 8) * 68 + c]) =
                    make_float2(accO[mt][nt][2], accO[mt][nt][3]);
            }
        }
    }
    __syncthreads();
    if (wn == 1) {
#pragma unroll
        for (int mt = 0; mt < 2; mt++) {
            const int r = wm * 32 + mt * 16 + g;
#pragma unroll
            for (int nt = 0; nt < 8; nt++) {
                const int c = nt * 8 + 2 * tig;
                float2 a = *reinterpret_cast<float2*>(&sRed[r * 68 + c]);
                *reinterpret_cast<float2*>(&sRed[r * 68 + c]) =
                    make_float2(a.x + accO[mt][nt][0], a.y + accO[mt][nt][1]);
                float2 d = *reinterpret_cast<float2*>(&sRed[(r + 8) * 68 + c]);
                *reinterpret_cast<float2*>(&sRed[(r + 8) * 68 + c]) =
                    make_float2(d.x + accO[mt][nt][2], d.y + accO[mt][nt][3]);
            }
        }
    }
    __syncthreads();
    {
        const int row = tid >> 1, cb = (tid & 1) * 32;
        float* cw = ctx_out + (size_t)(b * S_LEN + q0 + row) * HID + h * HD + cb;
        const float* rr = sRed + row * 68 + cb;
#pragma unroll
        for (int i = 0; i < 8; i++)
            *reinterpret_cast<float4*>(cw + 4 * i) =
                *reinterpret_cast<const float4*>(rr + 4 * i);
    }
}

// ============================================================================
// launch
// ============================================================================
extern "C" void kernel_launch(void* const* d_in, const int* in_sizes, int n_in,
                              void* d_out, int out_size)
{
    const float* X  = (const float*)d_in[0];
    const float* Wq = (const float*)d_in[1];
    const float* bq = (const float*)d_in[2];
    const float* Wk = (const float*)d_in[3];
    const float* bk = (const float*)d_in[4];
    const float* Wv = (const float*)d_in[5];
    const float* bv = (const float*)d_in[6];

    float* ctx   = (float*)d_out;                         // [2,2048,1024]
    float* probs = ctx + (size_t)BATCH * S_LEN * HID;     // [2,16,2048,2048]

    cvt_kernel<<<(unsigned)((NCVT + 255) / 256), 256>>>(X, Wq, Wk, Wv);

    cudaFuncSetAttribute(qkv_kernel, cudaFuncAttributeMaxDynamicSharedMemorySize,
                         QKV_SMEM);
    qkv_kernel<<<dim3(HID / 128, M_TOT / 128, 3), 256, QKV_SMEM>>>(bq, bk, bv);

    cudaFuncSetAttribute(attn_kernel, cudaFuncAttributeMaxDynamicSharedMemorySize,
                         ATTN_SMEM);
    attn_kernel<<<dim3(S_LEN / 128, NH, BATCH), 256, ATTN_SMEM>>>(ctx, probs);
}